// round 11
// baseline (speedup 1.0000x reference)
#include <cuda_runtime.h>
#include <cstdint>

// ---------------------------------------------------------------------------
// UniformAssigner, 2-launch persistent-fused design.
//  k_fused : phase 1  branch-free gate sweep (4x u32 masks / anchor, 2 anchors
//                     per thread) + exact-IoU epilogue appending candidates to
//                     128 bucketed buffers (independent atomicAdd + stores).
//            barrier  software grid barrier (all 391 blocks co-resident).
//            phase 2  blocks 0..127 drain their bucket: s3-filtered atomicMax
//                     cascade into per-gt top-4 (lock-free, monotone slots).
//            barrier
//            phase 3  block 0 scatters the <=512 winners into g_assigned.
//  k_final : labels + bboxes (out[0:N]=labels, out[N:5N]=bboxes); block 0 also
//            re-zeroes all mutable state for the next graph replay.
// ---------------------------------------------------------------------------

#define MAXM  128
#define NBUCK 128
#define BCAP  4096
#define MAXN  (1u << 20)
typedef unsigned long long ull;

__device__ ull g_topk[MAXM * 4];          // packed (iou_bits<<32|idx), 0=empty
__device__ int g_assigned[MAXN];
__device__ int g_bcnt[NBUCK];
__device__ ull g_bkey[NBUCK * BCAP];
__device__ int g_bgid[NBUCK * BCAP];
__device__ int g_arr[2];                  // barrier arrive counters
__device__ volatile int g_rel[2];         // barrier release flags

// lock-free top-4 insert; slots monotone non-decreasing, pairwise sorted.
__device__ __forceinline__ void cascade(ull* slots, ull key) {
#pragma unroll
    for (int s = 0; s < 4; s++) {
        ull prev = atomicMax(&slots[s], key);
        if (prev == 0ULL) break;          // landed in empty slot
        key = prev < key ? prev : key;    // push displaced smaller key down
    }
}

// software grid barrier: valid because grid (391 blocks) <= one wave.
__device__ __forceinline__ void grid_barrier(int which, int nb) {
    __syncthreads();
    if (threadIdx.x == 0) {
        __threadfence();
        int old = atomicAdd(&g_arr[which], 1);
        if (old == nb - 1) {
            g_rel[which] = 1;             // release (fence above orders data)
        } else {
            while (g_rel[which] == 0) __nanosleep(100);
        }
        __threadfence();                  // acquire side
    }
    __syncthreads();
}

// ---------------------------------------------------------------- fused -----
__global__ void __launch_bounds__(256)
k_fused(const float4* __restrict__ anchors, const float4* __restrict__ gts,
        int N, int M) {
    __shared__ float4 sbox[MAXM];
    __shared__ float  sarea[MAXM];
    __shared__ float  sthr[MAXM];
    for (int g = threadIdx.x; g < M; g += blockDim.x) {
        float4 b  = gts[g];
        float  ar = (b.z - b.x) * (b.w - b.y);
        sbox[g]  = b;
        sarea[g] = ar;
        sthr[g]  = 0.12f * ar;
    }
    __syncthreads();

    const int nb = gridDim.x;
    const int T  = nb * blockDim.x;
    const int i0 = blockIdx.x * blockDim.x + threadIdx.x;
    const int i1 = i0 + T;
    const int bk = blockIdx.x & (NBUCK - 1);

    float4 a0 = (i0 < N) ? anchors[i0] : make_float4(3e9f, 3e9f, 2e9f, 2e9f);
    float4 a1 = (i1 < N) ? anchors[i1] : make_float4(3e9f, 3e9f, 2e9f, 2e9f);
    const float areaA0 = (a0.z - a0.x) * (a0.w - a0.y);
    const float areaA1 = (a1.z - a1.x) * (a1.w - a1.y);
    const float tA0 = 0.12f * areaA0;
    const float tA1 = 0.12f * areaA1;

    // ---- phase 1a: branch-free sweep, 4x u32 masks per anchor ------------
    unsigned msk0[4] = {0, 0, 0, 0};
    unsigned msk1[4] = {0, 0, 0, 0};
#pragma unroll
    for (int w = 0; w < 4; w++) {
        int gbase = w * 32;
        int lim   = M - gbase;
        if (lim <= 0) break;
        if (lim > 32) lim = 32;
        unsigned m0 = 0, m1 = 0;
#pragma unroll 4
        for (int gg = 0; gg < lim; gg++) {
            float4 b   = sbox[gbase + gg];
            float  thr = sthr[gbase + gg];
            // clamped-extent product; thr >= 0.12*128 > 0 subsumes positivity
            float in0 = fmaxf(fminf(a0.z, b.z) - fmaxf(a0.x, b.x), 0.0f) *
                        fmaxf(fminf(a0.w, b.w) - fmaxf(a0.y, b.y), 0.0f);
            float in1 = fmaxf(fminf(a1.z, b.z) - fmaxf(a1.x, b.x), 0.0f) *
                        fmaxf(fminf(a1.w, b.w) - fmaxf(a1.y, b.y), 0.0f);
            m0 |= (unsigned)(in0 >= tA0 + thr) << gg;
            m1 |= (unsigned)(in1 >= tA1 + thr) << gg;
        }
        msk0[w] = m0;
        msk1[w] = m1;
    }

    // ---- phase 1b: exact reference math on rare candidates ---------------
    int ign0 = 0, ign1 = 0;
#pragma unroll
    for (int w = 0; w < 4; w++) {
        unsigned m = msk0[w];
        while (m) {
            int g = w * 32 + __ffs(m) - 1;
            m &= m - 1;
            float4 b = sbox[g];
            float iw    = fminf(a0.z, b.z) - fmaxf(a0.x, b.x);
            float ih    = fminf(a0.w, b.w) - fmaxf(a0.y, b.y);
            float inter = fmaxf(iw, 0.0f) * fmaxf(ih, 0.0f);
            float uni   = (areaA0 + sarea[g]) - inter;
            float iou   = inter / fmaxf(uni, 1e-7f);   // exact ref expression
            ign0 |= (iou >= 0.7f);
            if (iou >= 0.15f) {
                ull key = ((ull)__float_as_uint(iou) << 32) | (unsigned)i0;
                int slot = atomicAdd(&g_bcnt[bk], 1);
                if (slot < BCAP) {
                    g_bkey[bk * BCAP + slot] = key;
                    g_bgid[bk * BCAP + slot] = g;
                } else {
                    cascade(&g_topk[g * 4], key);      // rare overflow path
                }
            }
        }
        m = msk1[w];
        while (m) {
            int g = w * 32 + __ffs(m) - 1;
            m &= m - 1;
            float4 b = sbox[g];
            float iw    = fminf(a1.z, b.z) - fmaxf(a1.x, b.x);
            float ih    = fminf(a1.w, b.w) - fmaxf(a1.y, b.y);
            float inter = fmaxf(iw, 0.0f) * fmaxf(ih, 0.0f);
            float uni   = (areaA1 + sarea[g]) - inter;
            float iou   = inter / fmaxf(uni, 1e-7f);
            ign1 |= (iou >= 0.7f);
            if (iou >= 0.15f) {
                ull key = ((ull)__float_as_uint(iou) << 32) | (unsigned)i1;
                int slot = atomicAdd(&g_bcnt[bk], 1);
                if (slot < BCAP) {
                    g_bkey[bk * BCAP + slot] = key;
                    g_bgid[bk * BCAP + slot] = g;
                } else {
                    cascade(&g_topk[g * 4], key);
                }
            }
        }
    }

    if (i0 < N) g_assigned[i0] = ign0 ? -1 : 0;
    if (i1 < N) g_assigned[i1] = ign1 ? -1 : 0;

    // ---- barrier 1: all appends + baselines visible ----------------------
    grid_barrier(0, nb);

    // ---- phase 2: drain buckets into per-gt top-4 ------------------------
    if (blockIdx.x < NBUCK) {
        int b   = blockIdx.x;
        int cnt = g_bcnt[b];
        if (cnt > BCAP) cnt = BCAP;
        for (int j = threadIdx.x; j < cnt; j += blockDim.x) {
            ull key = g_bkey[b * BCAP + j];
            int g   = g_bgid[b * BCAP + j];
            ull* slots = &g_topk[g * 4];
            // stale slot[3] only under-filters (slots monotone) -> safe.
            ull s3;
            asm volatile("ld.global.cg.u64 %0, [%1];" : "=l"(s3) : "l"(slots + 3));
            if (key > s3) cascade(slots, key);
        }
    }

    // ---- barrier 2: top-4 final ------------------------------------------
    grid_barrier(1, nb);

    // ---- phase 3: scatter winners (block 0) ------------------------------
    if (blockIdx.x == 0) {
        for (int i = threadIdx.x; i < M * 4; i += blockDim.x) {
            ull key = g_topk[i];
            if (key == 0ULL) continue;
            float iou = __uint_as_float((unsigned)(key >> 32));
            if (iou >= 0.15f)
                atomicMax(&g_assigned[(int)(key & 0xffffffffULL)], i / 4 + 1);
        }
    }
}

// ------------------------------------------------------------ finalize ------
__global__ void __launch_bounds__(256)
k_final(const float4* __restrict__ gts, const int* __restrict__ labels,
        float* __restrict__ out, int N, int M) {
    // block 0: re-zero mutable state for the next graph replay (nothing in
    // this kernel reads these arrays; zero-init covers execution #1).
    if (blockIdx.x == 0) {
        for (int i = threadIdx.x; i < MAXM * 4; i += blockDim.x) g_topk[i] = 0ULL;
        for (int i = threadIdx.x; i < NBUCK; i += blockDim.x)    g_bcnt[i] = 0;
        if (threadIdx.x == 0) {
            g_arr[0] = 0; g_arr[1] = 0;
            g_rel[0] = 0; g_rel[1] = 0;
        }
    }

    const int i = blockIdx.x * blockDim.x + threadIdx.x;
    if (i >= N) return;
    int a = g_assigned[i];
    float  lab;
    float4 bb;
    if (a > 0) {
        lab = (float)labels[a - 1];
        bb  = gts[a - 1];
    } else {
        lab = (a == 0) ? 0.0f : -1.0f;
        bb  = make_float4(-1.0f, -1.0f, -1.0f, -1.0f);
    }
    out[i] = lab;
    if ((N & 3) == 0) {
        reinterpret_cast<float4*>(out + N)[i] = bb;   // out+N is 16B-aligned
    } else {
        float* p = out + N + 4 * i;
        p[0] = bb.x; p[1] = bb.y; p[2] = bb.z; p[3] = bb.w;
    }
}

// --------------------------------------------------------------------------
extern "C" void kernel_launch(void* const* d_in, const int* in_sizes, int n_in,
                              void* d_out, int out_size) {
    const float4* anchors = (const float4*)d_in[0];
    const float4* gts     = (const float4*)d_in[1];
    const int*    labels  = (const int*)d_in[2];
    int N = in_sizes[0] / 4;
    int M = in_sizes[1] / 4;
    float* out = (float*)d_out;

    int nb = (N + 511) / 512;        // 391 for N=200000: single co-resident wave
    k_fused<<<nb, 256>>>(anchors, gts, N, M);
    k_final<<<(N + 255) / 256, 256>>>(gts, labels, out, N, M);
}

// round 12
// speedup vs baseline: 1.4209x; 1.4209x over previous
#include <cuda_runtime.h>
#include <cstdint>

// ---------------------------------------------------------------------------
// UniformAssigner — proven flat chassis (R5), 3 launches.
//  k_main  : 2 anchors/thread; branch-free sweep builds 4x u32 candidate
//            masks per anchor via m = m*2 + p (IMAD form). Epilogue: exact
//            reference IoU on ~0.5 bits/thread, ign flag, lock-free per-gt
//            top-4 (s3-filtered atomicMax cascade).
//  k_scatter: <=512 entries -> atomicMax gt_id onto assigned[anchor].
//  k_final : labels + bboxes (out[0:N]=labels, out[N:5N]=bboxes); block 0
//            re-zeroes g_topk for the next graph replay (zero-init covers
//            the first execution; scatter precedes final, so no race).
// ---------------------------------------------------------------------------

#define MAXM 128
#define MAXN (1u << 20)
typedef unsigned long long ull;

__device__ ull g_topk[MAXM * 4];      // packed (iou_bits<<32|idx), 0 = empty
__device__ int g_assigned[MAXN];      // baseline 0/-1, then gt ids

// lock-free top-4 insert; slots monotone non-decreasing, pairwise sorted.
__device__ __forceinline__ void topk_insert(int g, float iou, unsigned idx) {
    ull key = ((ull)__float_as_uint(iou) << 32) | idx;
    ull* slots = &g_topk[g * 4];
    // stale slot[3] read can only be <= current -> skip on key<=read is safe.
    ull s3;
    asm volatile("ld.global.cg.u64 %0, [%1];" : "=l"(s3) : "l"(slots + 3));
    if (key > s3) {
#pragma unroll
        for (int s = 0; s < 4; s++) {
            ull prev = atomicMax(&slots[s], key);
            if (prev == 0ULL) break;        // landed in an empty slot
            key = prev < key ? prev : key;  // push displaced smaller key down
        }
    }
}

// ---------------------------------------------------------------- main ------
__global__ void __launch_bounds__(256)
k_main(const float4* __restrict__ anchors, const float4* __restrict__ gts,
       int N, int M) {
    __shared__ float4 sbox[MAXM];
    __shared__ float  sarea[MAXM];   // exact gt area (epilogue / union)
    __shared__ float  sthr[MAXM];    // 0.12 * gt area (conservative gate)
    for (int g = threadIdx.x; g < M; g += blockDim.x) {
        float4 b  = gts[g];
        float  ar = (b.z - b.x) * (b.w - b.y);
        sbox[g]  = b;
        sarea[g] = ar;
        sthr[g]  = 0.12f * ar;
    }
    __syncthreads();

    const int T  = gridDim.x * blockDim.x;
    const int i0 = blockIdx.x * blockDim.x + threadIdx.x;
    const int i1 = i0 + T;

    float4 a0 = (i0 < N) ? anchors[i0] : make_float4(3e9f, 3e9f, 2e9f, 2e9f);
    float4 a1 = (i1 < N) ? anchors[i1] : make_float4(3e9f, 3e9f, 2e9f, 2e9f);
    const float areaA0 = (a0.z - a0.x) * (a0.w - a0.y);
    const float areaA1 = (a1.z - a1.x) * (a1.w - a1.y);
    const float tA0 = 0.12f * areaA0;
    const float tA1 = 0.12f * areaA1;

    // ---- branch-free sweep: 4x u32 masks per anchor, IMAD accumulation ---
    // gate: max(iw,0)*ih >= tA + thr.  thr >= 0.12*128 > 0, and a single
    // clamp kills the (-)*(-) false positive:
    //   ih<0        -> product <= 0   < thr
    //   iw<0, ih>0  -> 0*ih    =  0   < thr
    // true candidates (iou>=0.15 => both extents>0) are never dropped.
    unsigned msk0[4], msk1[4];
#pragma unroll
    for (int w = 0; w < 4; w++) {
        int base = w * 32;
        unsigned m0 = 0, m1 = 0;
        if (base < M) {
            int lim = M - base;
            if (lim > 32) lim = 32;
#pragma unroll 4
            for (int j = 0; j < lim; j++) {
                float4 b   = sbox[base + j];
                float  thr = sthr[base + j];
                float iw0 = fminf(a0.z, b.z) - fmaxf(a0.x, b.x);
                float ih0 = fminf(a0.w, b.w) - fmaxf(a0.y, b.y);
                float in0 = fmaxf(iw0, 0.0f) * ih0;
                float iw1 = fminf(a1.z, b.z) - fmaxf(a1.x, b.x);
                float ih1 = fminf(a1.w, b.w) - fmaxf(a1.y, b.y);
                float in1 = fmaxf(iw1, 0.0f) * ih1;
                m0 = m0 * 2u + (unsigned)(in0 >= tA0 + thr);  // IMAD
                m1 = m1 * 2u + (unsigned)(in1 >= tA1 + thr);
            }
            if (lim < 32) {               // normalize: bit(31-j) <-> g=base+j
                m0 <<= (32 - lim);
                m1 <<= (32 - lim);
            }
        }
        msk0[w] = m0;
        msk1[w] = m1;
    }

    // ---- epilogue: exact reference math on rare candidates ---------------
    int ign0 = 0, ign1 = 0;
#pragma unroll
    for (int w = 0; w < 4; w++) {
        int base = w * 32;
        unsigned m = msk0[w];
        while (m) {
            int j = __clz(m);
            m &= ~(0x80000000u >> j);
            int g = base + j;
            float4 b = sbox[g];
            float iw    = fminf(a0.z, b.z) - fmaxf(a0.x, b.x);
            float ih    = fminf(a0.w, b.w) - fmaxf(a0.y, b.y);
            float inter = fmaxf(iw, 0.0f) * fmaxf(ih, 0.0f);
            float uni   = (areaA0 + sarea[g]) - inter;
            float iou   = inter / fmaxf(uni, 1e-7f);   // exact ref expression
            ign0 |= (iou >= 0.7f);
            if (iou >= 0.15f) topk_insert(g, iou, (unsigned)i0);
        }
        m = msk1[w];
        while (m) {
            int j = __clz(m);
            m &= ~(0x80000000u >> j);
            int g = base + j;
            float4 b = sbox[g];
            float iw    = fminf(a1.z, b.z) - fmaxf(a1.x, b.x);
            float ih    = fminf(a1.w, b.w) - fmaxf(a1.y, b.y);
            float inter = fmaxf(iw, 0.0f) * fmaxf(ih, 0.0f);
            float uni   = (areaA1 + sarea[g]) - inter;
            float iou   = inter / fmaxf(uni, 1e-7f);
            ign1 |= (iou >= 0.7f);
            if (iou >= 0.15f) topk_insert(g, iou, (unsigned)i1);
        }
    }

    if (i0 < N) g_assigned[i0] = ign0 ? -1 : 0;
    if (i1 < N) g_assigned[i1] = ign1 ? -1 : 0;
}

// ------------------------------------------------------------- scatter ------
__global__ void k_scatter(int M) {
    int i = blockIdx.x * blockDim.x + threadIdx.x;
    if (i >= M * 4) return;
    ull key = g_topk[i];
    if (key == 0ULL) return;
    float iou = __uint_as_float((unsigned)(key >> 32));
    if (iou >= 0.15f) {
        int idx = (int)(key & 0xffffffffULL);
        atomicMax(&g_assigned[idx], i / 4 + 1);
    }
}

// ------------------------------------------------------------ finalize ------
__global__ void __launch_bounds__(256)
k_final(const float4* __restrict__ gts, const int* __restrict__ labels,
        float* __restrict__ out, int N) {
    // block 0: re-zero g_topk for the next graph replay (scatter already ran;
    // nothing in this kernel reads g_topk).
    if (blockIdx.x == 0) {
#pragma unroll
        for (int k = 0; k < 2; k++) g_topk[threadIdx.x + k * 256] = 0ULL;
    }

    const int i = blockIdx.x * blockDim.x + threadIdx.x;
    if (i >= N) return;
    int a = g_assigned[i];
    float  lab;
    float4 bb;
    if (a > 0) {
        lab = (float)labels[a - 1];
        bb  = gts[a - 1];
    } else {
        lab = (a == 0) ? 0.0f : -1.0f;
        bb  = make_float4(-1.0f, -1.0f, -1.0f, -1.0f);
    }
    out[i] = lab;
    if ((N & 3) == 0) {
        reinterpret_cast<float4*>(out + N)[i] = bb;   // out+N is 16B-aligned
    } else {
        float* p = out + N + 4 * i;
        p[0] = bb.x; p[1] = bb.y; p[2] = bb.z; p[3] = bb.w;
    }
}

// --------------------------------------------------------------------------
extern "C" void kernel_launch(void* const* d_in, const int* in_sizes, int n_in,
                              void* d_out, int out_size) {
    const float4* anchors = (const float4*)d_in[0];
    const float4* gts     = (const float4*)d_in[1];
    const int*    labels  = (const int*)d_in[2];
    int N = in_sizes[0] / 4;
    int M = in_sizes[1] / 4;
    float* out = (float*)d_out;

    k_main<<<(N + 511) / 512, 256>>>(anchors, gts, N, M);
    k_scatter<<<(M * 4 + 255) / 256, 256>>>(M);
    k_final<<<(N + 255) / 256, 256>>>(gts, labels, out, N);
}